// round 14
// baseline (speedup 1.0000x reference)
#include <cuda_runtime.h>
#include <cuda_bf16.h>
#include <cstdint>
#include <math.h>

// Problem constants
#define PLANE   (2048*2048)       // 4,194,304 pixels per channel plane
#define NBINS   4913              // 17^3 distinct compact keys (289a+17b+c)
#define NFEAT   20

#define NBLOCKS      148
#define NTHREADS     1024
#define LUT_THREADS  128                       // warps 0-3: LUT staging
#define HIST_THREADS (NTHREADS - LUT_THREADS)  // 896: histogram mainloop
#define NWARPS       (NTHREADS / 32)

#define MODE_INT8   0
#define MODE_INT32  1
#define MODE_FP32   2
#define MODE_BF16   3

// Dynamic smem layout (words):
//   [0, NBINS*10)              packed int8 LUT: bin j -> 10 words
//                              (words 10j..10j+4 = msb[20] bytes, 10j+5..10j+9 = lsb[20])
//   [NBINS*10, NBINS*11)       packed hist: word j = hm[j] | hl[j]<<16
//   [NBINS*11, +NWARPS*NFEAT)  per-warp partial sums
#define SM_LUT   0
#define SM_HIST  (NBINS * 10)
#define SM_PART  (NBINS * 11)
#define SMEM_WORDS (NBINS * 11 + NWARPS * NFEAT)
#define SMEM_BYTES (SMEM_WORDS * 4)            // ~218.7 KB

// ---------------------------------------------------------------------------
// Global scratch. Zero at module load; the final (ticket-elected) block
// re-zeroes everything it consumes -> invariant across graph replays.
// Deterministic: integer sums, order-independent.
// ---------------------------------------------------------------------------
__device__ int          g_accum[NFEAT];
__device__ unsigned int g_ticket;

// Scalar fetch for non-int32 upcast modes (fallback path only).
__device__ __forceinline__ int fetch_lut(const void* __restrict__ tab, int mode, long long e)
{
    switch (mode) {
        case MODE_FP32:  return (int)((const float*)tab)[e];
        case MODE_BF16:  return (int)__bfloat162float(((const __nv_bfloat16*)tab)[e]);
        default:         return (int)((const signed char*)tab)[e];
    }
}

__device__ __forceinline__ unsigned int pack4(int a, int b, int c, int d)
{
    return (unsigned)(a & 0xFF) | ((unsigned)(b & 0xFF) << 8) |
           ((unsigned)(c & 0xFF) << 16) | ((unsigned)(d & 0xFF) << 24);
}

// ---------------------------------------------------------------------------
// SINGLE kernel. Per block:
//   warps 0-3 : sniff LUT dtype, stage FULL LUT into smem as int8 (786KB L2
//               reads spread across the hist window; L2-resident after the
//               first touch).
//   warps 4-31: packed-uint16 shared-ATOMS histogram of this block's pixel
//               slice (msb count = low half, lsb count = high half; per-block
//               counts < 2^16 -> no carry).
//   __syncthreads, then ALL warps: dot(local hist, LUT) -> REDUX -> one
//   global atomic per feature -> ticket; LAST block quantizes + writes out.
// NO global histogram, NO flush, NO inter-block waiting (linearity:
// sum_b hist_b . LUT == hist_global . LUT).
// ---------------------------------------------------------------------------
__global__ void __launch_bounds__(NTHREADS, 1)
fused_kernel(const float* __restrict__ x_in, const float* __restrict__ x_s,
             const void* __restrict__ msb, const void* __restrict__ lsb,
             float* __restrict__ out)
{
    extern __shared__ unsigned int smem[];
    unsigned int* __restrict__ lut  = smem + SM_LUT;
    unsigned int* __restrict__ hist = smem + SM_HIST;
    int*          __restrict__ part = (int*)(smem + SM_PART);

    const int tid  = threadIdx.x;
    const int wid  = tid >> 5;
    const int lane = tid & 31;

    for (int k = tid; k < NBINS; k += NTHREADS) hist[k] = 0u;
    __syncthreads();

    if (tid < LUT_THREADS) {
        // ---- dtype sniff (each of the 4 warps redundantly; batched loads) ----
        int mode;
        {
            const int* w = (const int*)msb;
            int v[8];
            #pragma unroll
            for (int s = 0; s < 8; s++) v[s] = w[lane + 32 * s];
            bool small = true, flt = true, bfl = true;
            #pragma unroll
            for (int s = 0; s < 8; s++) {
                int x = v[s];
                if (x < -32 || x > 31) small = false;
                float f = __int_as_float(x);
                if (!(isfinite(f) && f == truncf(f) && fabsf(f) <= 32.f)) flt = false;
                unsigned u = (unsigned)x;
                float h0 = __bfloat162float(__ushort_as_bfloat16((unsigned short)(u & 0xFFFFu)));
                float h1 = __bfloat162float(__ushort_as_bfloat16((unsigned short)(u >> 16)));
                if (!(isfinite(h0) && h0 == truncf(h0) && fabsf(h0) <= 32.f &&
                      isfinite(h1) && h1 == truncf(h1) && fabsf(h1) <= 32.f)) bfl = false;
            }
            if      (__all_sync(0xffffffffu, small)) mode = MODE_INT32;
            else if (__all_sync(0xffffffffu, flt))   mode = MODE_FP32;
            else if (__all_sync(0xffffffffu, bfl))   mode = MODE_BF16;
            else                                     mode = MODE_INT8;
        }
        // ---- stage the FULL LUT (4913 bins x 5 chunks) into smem as int8 ----
        if (mode == MODE_INT32) {
            const int4* m4 = (const int4*)msb;
            const int4* l4 = (const int4*)lsb;
            for (int t = tid; t < NBINS * 5; t += LUT_THREADS) {
                const int j = t / 5, q = t - 5 * j;
                int4 a = m4[80L * j + q];
                int4 b = l4[80L * j + q];
                lut[j * 10 + q]     = pack4(a.x, a.y, a.z, a.w);
                lut[j * 10 + 5 + q] = pack4(b.x, b.y, b.z, b.w);
            }
        } else {
            for (int t = tid; t < NBINS * 5; t += LUT_THREADS) {
                const int j = t / 5, q = t - 5 * j;
                const long long e = 320LL * j + 4LL * q;
                lut[j * 10 + q]     = pack4(fetch_lut(msb, mode, e + 0), fetch_lut(msb, mode, e + 1),
                                            fetch_lut(msb, mode, e + 2), fetch_lut(msb, mode, e + 3));
                lut[j * 10 + 5 + q] = pack4(fetch_lut(lsb, mode, e + 0), fetch_lut(lsb, mode, e + 1),
                                            fetch_lut(lsb, mode, e + 2), fetch_lut(lsb, mode, e + 3));
            }
        }
    } else {
        // ---- histogram mainloop: 896 workers per block ----
        const float4* __restrict__ a0 = (const float4*)(x_in);
        const float4* __restrict__ a1 = (const float4*)(x_in + PLANE);
        const float4* __restrict__ a2 = (const float4*)(x_in + 2 * PLANE);
        const float4* __restrict__ b0 = (const float4*)(x_s);
        const float4* __restrict__ b1 = (const float4*)(x_s + PLANE);
        const float4* __restrict__ b2 = (const float4*)(x_s + 2 * PLANE);

        const int NP     = PLANE / 8;                      // pairs of float4
        const int worker = blockIdx.x * HIST_THREADS + (tid - LUT_THREADS);
        const int stride = NBLOCKS * HIST_THREADS;

        for (int p = worker; p < NP; p += stride) {
            const int i0 = 2 * p, i1 = 2 * p + 1;
            float4 va0 = __ldcs(&a0[i0]); float4 va1 = __ldcs(&a0[i1]);
            float4 vb0 = __ldcs(&a1[i0]); float4 vb1 = __ldcs(&a1[i1]);
            float4 vc0 = __ldcs(&a2[i0]); float4 vc1 = __ldcs(&a2[i1]);
            float4 wa0 = __ldcs(&b0[i0]); float4 wa1 = __ldcs(&b0[i1]);
            float4 wb0 = __ldcs(&b1[i0]); float4 wb1 = __ldcs(&b1[i1]);
            float4 wc0 = __ldcs(&b2[i0]); float4 wc1 = __ldcs(&b2[i1]);

            // key = 289*a + 17*b + c  (exact in fp32: max 4912 < 2^24)
            // msb -> +1 (low half), lsb -> +0x10000 (high half); no carry
            atomicAdd(&hist[(int)fmaf(289.f, va0.x, fmaf(17.f, vb0.x, vc0.x))], 1u);
            atomicAdd(&hist[(int)fmaf(289.f, va0.y, fmaf(17.f, vb0.y, vc0.y))], 1u);
            atomicAdd(&hist[(int)fmaf(289.f, va0.z, fmaf(17.f, vb0.z, vc0.z))], 1u);
            atomicAdd(&hist[(int)fmaf(289.f, va0.w, fmaf(17.f, vb0.w, vc0.w))], 1u);
            atomicAdd(&hist[(int)fmaf(289.f, va1.x, fmaf(17.f, vb1.x, vc1.x))], 1u);
            atomicAdd(&hist[(int)fmaf(289.f, va1.y, fmaf(17.f, vb1.y, vc1.y))], 1u);
            atomicAdd(&hist[(int)fmaf(289.f, va1.z, fmaf(17.f, vb1.z, vc1.z))], 1u);
            atomicAdd(&hist[(int)fmaf(289.f, va1.w, fmaf(17.f, vb1.w, vc1.w))], 1u);

            atomicAdd(&hist[(int)fmaf(289.f, wa0.x, fmaf(17.f, wb0.x, wc0.x))], 65536u);
            atomicAdd(&hist[(int)fmaf(289.f, wa0.y, fmaf(17.f, wb0.y, wc0.y))], 65536u);
            atomicAdd(&hist[(int)fmaf(289.f, wa0.z, fmaf(17.f, wb0.z, wc0.z))], 65536u);
            atomicAdd(&hist[(int)fmaf(289.f, wa0.w, fmaf(17.f, wb0.w, wc0.w))], 65536u);
            atomicAdd(&hist[(int)fmaf(289.f, wa1.x, fmaf(17.f, wb1.x, wc1.x))], 65536u);
            atomicAdd(&hist[(int)fmaf(289.f, wa1.y, fmaf(17.f, wb1.y, wc1.y))], 65536u);
            atomicAdd(&hist[(int)fmaf(289.f, wa1.z, fmaf(17.f, wb1.z, wc1.z))], 65536u);
            atomicAdd(&hist[(int)fmaf(289.f, wa1.w, fmaf(17.f, wb1.w, wc1.w))], 65536u);
        }
    }
    __syncthreads();

    // ---------------- dot(local hist, LUT): all 1024 threads ----------------
    int vals[NFEAT];
    #pragma unroll
    for (int f = 0; f < NFEAT; f++) vals[f] = 0;

    for (int j = tid; j < NBINS; j += NTHREADS) {
        const unsigned int w = hist[j];
        if (w == 0u) continue;
        const int cm = (int)(w & 0xFFFFu);
        const int cl = (int)(w >> 16);
        const unsigned int* row = &lut[j * 10];
        #pragma unroll
        for (int q = 0; q < 5; q++) {
            const unsigned int um = row[q];
            const unsigned int ul = row[5 + q];
            #pragma unroll
            for (int k = 0; k < 4; k++) {
                const int vm = ((int)(um << (24 - 8 * k))) >> 24;  // sign-extend byte k
                const int vl = ((int)(ul << (24 - 8 * k))) >> 24;
                vals[4 * q + k] += cm * vm + cl * vl;
            }
        }
    }

    // Warp-level sums via REDUX; lane f keeps feature f's warp sum.
    int mine = 0;
    #pragma unroll
    for (int f = 0; f < NFEAT; f++) {
        int s = __reduce_add_sync(0xffffffffu, vals[f]);
        if (lane == f) mine = s;
    }
    if (lane < NFEAT) part[wid * NFEAT + lane] = mine;
    __syncthreads();

    if (tid < NFEAT) {
        int r = 0;
        #pragma unroll
        for (int w = 0; w < NWARPS; w++) r += part[w * NFEAT + tid];
        atomicAdd(&g_accum[tid], r);
    }
    __threadfence();
    __syncthreads();

    __shared__ int s_last;
    if (tid == 0) {
        unsigned int t = atomicAdd(&g_ticket, 1u);
        s_last = (t == NBLOCKS - 1) ? 1 : 0;
    }
    __syncthreads();

    if (s_last && tid < NFEAT) {
        // Last finisher: all other blocks' adds are ordered before their
        // tickets -> coherent atomic read sees the full sum.
        int S = atomicAdd(&g_accum[tid], 0);
        g_accum[tid] = 0;                    // zero-on-consume
        if (tid == 0) g_ticket = 0u;
        // out = clip(round(mean*4)/4, -32, 31.75)
        //     = clamp(rint(S / 2^20), -128, 127) * 0.25   (exact in double)
        double q = rint((double)S / 1048576.0);
        q = fmin(fmax(q, -128.0), 127.0);
        out[tid] = (float)(q * 0.25);
    }
}

// ---------------------------------------------------------------------------
extern "C" void kernel_launch(void* const* d_in, const int* in_sizes, int n_in,
                              void* d_out, int out_size)
{
    const float* x_in = (const float*)d_in[0];
    const float* x_s  = (const float*)d_in[1];
    const void*  msb  = d_in[2];
    const void*  lsb  = d_in[3];
    float*       out  = (float*)d_out;

    static bool attr_set = false;     // host-side, idempotent, no device mem
    if (!attr_set) {
        cudaFuncSetAttribute(fused_kernel,
                             cudaFuncAttributeMaxDynamicSharedMemorySize, SMEM_BYTES);
        attr_set = true;
    }
    fused_kernel<<<NBLOCKS, NTHREADS, SMEM_BYTES>>>(x_in, x_s, msb, lsb, out);
}

// round 16
// speedup vs baseline: 1.7986x; 1.7986x over previous
#include <cuda_runtime.h>
#include <cuda_bf16.h>
#include <cstdint>
#include <math.h>

// Problem constants
#define PLANE   (2048*2048)       // 4,194,304 pixels per channel plane
#define NBINS   4913              // 17^3 distinct compact keys (289a+17b+c)
#define NFEAT   20

#define K1_HALF    148                   // blocks per tensor half
#define K1_BLOCKS  (2 * K1_HALF)         // 296 total; 2 co-resident per SM
#define K1_THREADS 1024
#define K2_THREADS 256
#define K2_WARPS   (K2_THREADS / 32)
#define K2_BLOCKS  ((NBINS + K2_THREADS - 1) / K2_THREADS)   // 20

#define MODE_INT8   0
#define MODE_INT32  1
#define MODE_FP32   2
#define MODE_BF16   3

// Staging work partition: 4913 bins x 5 int4 chunks = 24565 chunk-pairs
#define STAGE_TOTAL (NBINS * 5)
#define STAGE_PER_B ((STAGE_TOTAL + K1_HALF - 1) / K1_HALF)   // 166

// ---------------------------------------------------------------------------
// Global scratch. CUDA zeroes __device__ globals at module load. Invariant
// across launches / graph replays: g_hist, g_accum, g_ticket are ZERO on
// entry — kernel 2 re-zeroes everything it consumes. g_stage is fully
// overwritten every launch from constant inputs -> deterministic.
// ---------------------------------------------------------------------------
__device__ unsigned int g_hist[2 * NBINS];   // [msb bins | lsb bins]
__device__ int          g_accum[NFEAT];
__device__ unsigned int g_ticket;
// Compact, int32-normalized LUT rows: bin j -> 10 int4 = {msb[20] | lsb[20]}
__device__ int4         g_stage[NBINS * 10]; // 786 KB

// Scalar fetch for non-int32 upcast modes (fallback path only).
__device__ __forceinline__ int fetch_lut(const void* __restrict__ tab, int mode, long long e)
{
    switch (mode) {
        case MODE_FP32:  return (int)((const float*)tab)[e];
        case MODE_BF16:  return (int)__bfloat162float(((const __nv_bfloat16*)tab)[e]);
        default:         return (int)((const signed char*)tab)[e];
    }
}

// ---------------------------------------------------------------------------
// Kernel 1: SPLIT-TENSOR histogram. Block b < 148 histograms x_in (msb keys);
// b >= 148 histograms x_s (lsb keys). One 19.6KB shared hist + 6 loads/iter
// per block -> ~32 regs -> with __maxnreg__(32), TWO blocks per SM (2048
// threads, 2x in-flight loads vs the fused version at occ 52.7%/DRAM 66%).
// Traffic, ATOMS count and flush volume unchanged — only parallelism rises.
// First-half blocks' warp 0 also stages the LUT (R10 scheme, hidden).
// ---------------------------------------------------------------------------
__global__ void __maxnreg__(32)
hist_kernel(const float* __restrict__ x_in, const float* __restrict__ x_s,
            const void* __restrict__ msb, const void* __restrict__ lsb)
{
    __shared__ unsigned int h[NBINS];

    const int tid  = threadIdx.x;
    const int half = (blockIdx.x >= K1_HALF) ? 1 : 0;     // 0: x_in/msb, 1: x_s/lsb
    const int brel = blockIdx.x - half * K1_HALF;         // 0..147 within half

    for (int k = tid; k < NBINS; k += K1_THREADS) h[k] = 0u;
    __syncthreads();

    // --- warp 0 of first-half blocks: dtype sniff + LUT staging slice ---
    if (half == 0 && tid < 32) {
        const int lane = tid;
        const int* w = (const int*)msb;
        int v[8];
        #pragma unroll
        for (int s = 0; s < 8; s++) v[s] = w[lane + 32 * s];

        bool small = true, flt = true, bfl = true;
        #pragma unroll
        for (int s = 0; s < 8; s++) {
            int x = v[s];
            if (x < -32 || x > 31) small = false;
            float f = __int_as_float(x);
            if (!(isfinite(f) && f == truncf(f) && fabsf(f) <= 32.f)) flt = false;
            unsigned u = (unsigned)x;
            float h0 = __bfloat162float(__ushort_as_bfloat16((unsigned short)(u & 0xFFFFu)));
            float h1 = __bfloat162float(__ushort_as_bfloat16((unsigned short)(u >> 16)));
            if (!(isfinite(h0) && h0 == truncf(h0) && fabsf(h0) <= 32.f &&
                  isfinite(h1) && h1 == truncf(h1) && fabsf(h1) <= 32.f)) bfl = false;
        }
        int mode;
        if      (__all_sync(0xffffffffu, small)) mode = MODE_INT32;
        else if (__all_sync(0xffffffffu, flt))   mode = MODE_FP32;
        else if (__all_sync(0xffffffffu, bfl))   mode = MODE_BF16;
        else                                     mode = MODE_INT8;

        const int base = brel * STAGE_PER_B;
        int end = base + STAGE_PER_B; if (end > STAGE_TOTAL) end = STAGE_TOTAL;
        if (mode == MODE_INT32) {
            const int4* m4 = (const int4*)msb;
            const int4* l4 = (const int4*)lsb;
            for (int t = base + lane; t < end; t += 32) {
                const int j = t / 5, q = t - 5 * j;
                g_stage[j * 10 + q]     = m4[80L * j + q];
                g_stage[j * 10 + 5 + q] = l4[80L * j + q];
            }
        } else {
            for (int t = base + lane; t < end; t += 32) {
                const int j = t / 5, q = t - 5 * j;
                const long long e = 320LL * j + 4LL * q;
                int4 vm, vl;
                vm.x = fetch_lut(msb, mode, e + 0); vm.y = fetch_lut(msb, mode, e + 1);
                vm.z = fetch_lut(msb, mode, e + 2); vm.w = fetch_lut(msb, mode, e + 3);
                vl.x = fetch_lut(lsb, mode, e + 0); vl.y = fetch_lut(lsb, mode, e + 1);
                vl.z = fetch_lut(lsb, mode, e + 2); vl.w = fetch_lut(lsb, mode, e + 3);
                g_stage[j * 10 + q]     = vm;
                g_stage[j * 10 + 5 + q] = vl;
            }
        }
    }

    // ---------------- histogram of this block's tensor ----------------
    {
        const float* __restrict__ src = half ? x_s : x_in;
        const float4* __restrict__ a0 = (const float4*)(src);
        const float4* __restrict__ a1 = (const float4*)(src + PLANE);
        const float4* __restrict__ a2 = (const float4*)(src + 2 * PLANE);

        const int NP     = PLANE / 8;                  // pairs of float4 positions
        const int stride = K1_HALF * K1_THREADS;

        for (int p = brel * K1_THREADS + tid; p < NP; p += stride) {
            const int i0 = 2 * p, i1 = 2 * p + 1;
            // 6 independent streaming loads in flight per thread
            // (x2 blocks/SM -> same total MLP as the fused kernel, 2x warps).
            float4 va0 = __ldcs(&a0[i0]); float4 va1 = __ldcs(&a0[i1]);
            float4 vb0 = __ldcs(&a1[i0]); float4 vb1 = __ldcs(&a1[i1]);
            float4 vc0 = __ldcs(&a2[i0]); float4 vc1 = __ldcs(&a2[i1]);

            // key = 289*a + 17*b + c  (exact in fp32: max 4912 < 2^24)
            atomicAdd(&h[(int)fmaf(289.f, va0.x, fmaf(17.f, vb0.x, vc0.x))], 1u);
            atomicAdd(&h[(int)fmaf(289.f, va0.y, fmaf(17.f, vb0.y, vc0.y))], 1u);
            atomicAdd(&h[(int)fmaf(289.f, va0.z, fmaf(17.f, vb0.z, vc0.z))], 1u);
            atomicAdd(&h[(int)fmaf(289.f, va0.w, fmaf(17.f, vb0.w, vc0.w))], 1u);
            atomicAdd(&h[(int)fmaf(289.f, va1.x, fmaf(17.f, vb1.x, vc1.x))], 1u);
            atomicAdd(&h[(int)fmaf(289.f, va1.y, fmaf(17.f, vb1.y, vc1.y))], 1u);
            atomicAdd(&h[(int)fmaf(289.f, va1.z, fmaf(17.f, vb1.z, vc1.z))], 1u);
            atomicAdd(&h[(int)fmaf(289.f, va1.w, fmaf(17.f, vb1.w, vc1.w))], 1u);
        }
    }
    __syncthreads();

    // Flush into this half's global histogram (REDG, spread addresses).
    unsigned int* __restrict__ gh = g_hist + half * NBINS;
    for (int k = tid; k < NBINS; k += K1_THREADS) {
        unsigned int v = h[k];
        if (v) atomicAdd(&gh[k], v);
    }
}

// ---------------------------------------------------------------------------
// Kernel 2 (reduce + final): R10-measured-best, verbatim. Branch-free,
// fully coalesced: thread j issues 2 count loads + 10 CONTIGUOUS int4 loads
// from the normalized staging array (L2-warm), all independent -> single
// latency round. REDUX warp sums, one global atomic per feature, ticket
// finish. Consumed state re-zeroed for the next launch.
// All sums fit int32 (|S| <= 2 * 4.2M * 32 ~= 2.7e8 < 2^31).
// ---------------------------------------------------------------------------
__global__ void __launch_bounds__(K2_THREADS)
reduce_final_kernel(float* __restrict__ out)
{
    __shared__ int s_part[K2_WARPS][NFEAT];
    __shared__ int s_last;
    const int tid  = threadIdx.x;
    const int wid  = tid >> 5;
    const int lane = tid & 31;

    const int j = blockIdx.x * K2_THREADS + tid;
    const bool active = (j < NBINS);

    int cm = 0, cl = 0;
    int4 c[10];
    if (active) {
        cm = (int)g_hist[j];
        cl = (int)g_hist[NBINS + j];
        const int4* row = &g_stage[j * 10];
        #pragma unroll
        for (int q = 0; q < 10; q++) c[q] = row[q];   // 160B contiguous per thread
        g_hist[j] = 0u;                               // zero-on-consume
        g_hist[NBINS + j] = 0u;
    } else {
        #pragma unroll
        for (int q = 0; q < 10; q++) c[q] = make_int4(0, 0, 0, 0);
    }

    int vals[NFEAT];
    #pragma unroll
    for (int q = 0; q < 5; q++) {
        vals[4*q+0] = cm * c[q].x + cl * c[5+q].x;
        vals[4*q+1] = cm * c[q].y + cl * c[5+q].y;
        vals[4*q+2] = cm * c[q].z + cl * c[5+q].z;
        vals[4*q+3] = cm * c[q].w + cl * c[5+q].w;
    }

    // Warp-level sums via REDUX; lane f keeps feature f's warp sum.
    int mine = 0;
    #pragma unroll
    for (int f = 0; f < NFEAT; f++) {
        int s = __reduce_add_sync(0xffffffffu, vals[f]);
        if (lane == f) mine = s;
    }
    if (lane < NFEAT) s_part[wid][lane] = mine;
    __syncthreads();

    if (tid < NFEAT) {
        int r = 0;
        #pragma unroll
        for (int w = 0; w < K2_WARPS; w++) r += s_part[w][tid];
        atomicAdd(&g_accum[tid], r);
    }
    __threadfence();
    __syncthreads();

    if (tid == 0) {
        unsigned int t = atomicAdd(&g_ticket, 1u);
        s_last = (t == K2_BLOCKS - 1) ? 1 : 0;
    }
    __syncthreads();

    if (s_last && tid < NFEAT) {
        // Coherent read (L2 atomic), then reset for next launch.
        int S = atomicAdd(&g_accum[tid], 0);
        g_accum[tid] = 0;
        if (tid == 0) g_ticket = 0u;
        // out = clip(round(mean*4)/4, -32, 31.75)
        //     = clamp(rint(S / 2^20), -128, 127) * 0.25   (exact in double)
        double q = rint((double)S / 1048576.0);
        q = fmin(fmax(q, -128.0), 127.0);
        out[tid] = (float)(q * 0.25);
    }
}

// ---------------------------------------------------------------------------
extern "C" void kernel_launch(void* const* d_in, const int* in_sizes, int n_in,
                              void* d_out, int out_size)
{
    const float* x_in = (const float*)d_in[0];
    const float* x_s  = (const float*)d_in[1];
    const void*  msb  = d_in[2];
    const void*  lsb  = d_in[3];
    float*       out  = (float*)d_out;

    hist_kernel<<<K1_BLOCKS, K1_THREADS>>>(x_in, x_s, msb, lsb);
    reduce_final_kernel<<<K2_BLOCKS, K2_THREADS>>>(out);
}